// round 2
// baseline (speedup 1.0000x reference)
#include <cuda_runtime.h>

#define HDIM   64
#define NHEADS 4
#define QKDIM  256           // NHEADS * HDIM
#define N_SRC  50000
#define N_TGT  10000
#define N_E    250000
#define N_LBL  200000

typedef unsigned long long ull;

// ---------------- scratch (static device memory; no allocations) ----------------
__device__ float g_xs_a[N_SRC * HDIM];
__device__ float g_xs_b[N_SRC * HDIM];
__device__ float g_xt_a[N_TGT * HDIM];
__device__ float g_xt_b[N_TGT * HDIM];

__device__ float g_q_st[N_TGT * QKDIM];   // q of tgt nodes (st conv)
__device__ float g_k_ts[N_TGT * QKDIM];   // k of tgt nodes (ts conv)
__device__ float g_v_ts[N_TGT * QKDIM];
__device__ float g_q_ts[N_SRC * QKDIM];   // q of src nodes (ts conv)
__device__ float g_k_st[N_SRC * QKDIM];
__device__ float g_v_st[N_SRC * QKDIM];

__device__ float    g_sc_st[N_E * NHEADS];
__device__ float    g_sc_ts[N_E * NHEADS];
__device__ unsigned g_m_st[N_TGT * NHEADS];
__device__ float    g_d_st[N_TGT * NHEADS];
__device__ unsigned g_m_ts[N_SRC * NHEADS];
__device__ float    g_d_ts[N_SRC * NHEADS];

// ---------------- helpers ----------------
__device__ __forceinline__ unsigned f2o(float f) {
    unsigned u = __float_as_uint(f);
    return (u & 0x80000000u) ? ~u : (u | 0x80000000u);
}
__device__ __forceinline__ float o2f(unsigned u) {
    u = (u & 0x80000000u) ? (u & 0x7fffffffu) : ~u;
    return __uint_as_float(u);
}
// packed fp32x2 FMA (sm_103a; ptxas never emits this from C++)
__device__ __forceinline__ void fma2(ull& d, ull a, ull b) {
    asm("fma.rn.f32x2 %0, %1, %2, %3;" : "=l"(d) : "l"(a), "l"(b), "l"(d));
}
__device__ __forceinline__ float hsum2(ull p) {
    float lo, hi;
    asm("mov.b64 {%0, %1}, %2;" : "=f"(lo), "=f"(hi) : "l"(p));
    return lo + hi;
}

union F2U { ull u; float2 f; };

// ---------------- kernels ----------------
__global__ void zero4_kernel(float* __restrict__ a, int na, float* __restrict__ b, int nb,
                             float* __restrict__ c, int nc, float* __restrict__ d, int nd) {
    int i = blockIdx.x * blockDim.x + threadIdx.x;
    if (i < na) { a[i] = 0.0f; return; }
    i -= na;
    if (i < nb) { b[i] = 0.0f; return; }
    i -= nb;
    if (i < nc) { c[i] = 0.0f; return; }
    i -= nc;
    if (i < nd) d[i] = 0.0f;
}

__global__ void gather_rows(const float* __restrict__ emb, const int* __restrict__ ids,
                            float* __restrict__ out, int nrows) {
    int i = blockIdx.x * blockDim.x + threadIdx.x;
    int total = nrows * HDIM;
    if (i >= total) return;
    int row = i >> 6, d = i & 63;
    out[i] = emb[(size_t)ids[row] * HDIM + d];
}

// Fused projection GEMM: X[N,64] -> three [N,256] (q/k/v-like) + one [N,64] skip.
// 64x64 tile, K=64, 256 threads, 4x4 microtile, packed f32x2 FMA over k-pairs.
__global__ void proj_kernel(const float* __restrict__ X, int N, int relu_in,
                            const float* __restrict__ W0, const float* __restrict__ W1,
                            const float* __restrict__ W2, const float* __restrict__ W3,
                            const float* __restrict__ b0, const float* __restrict__ b1,
                            const float* __restrict__ b2, const float* __restrict__ b3,
                            float* __restrict__ o0, float* __restrict__ o1,
                            float* __restrict__ o2, float* __restrict__ o3) {
    __shared__ ull As2[64][32];   // [row][kpair] packed {X[r,2k], X[r,2k+1]}
    __shared__ ull Bs2[64][33];   // [col][kpair] packed {W[2k,c], W[2k+1,c]} (pad 33: no conflicts)

    int cb = blockIdx.y;                 // 0..12 (13 col blocks of 64)
    const float* W; const float* bias; float* out; int wstride, ostride, lcb;
    if (cb < 4)       { W = W0; bias = b0; out = o0; wstride = 256; ostride = 256; lcb = cb; }
    else if (cb < 8)  { W = W1; bias = b1; out = o1; wstride = 256; ostride = 256; lcb = cb - 4; }
    else if (cb < 12) { W = W2; bias = b2; out = o2; wstride = 256; ostride = 256; lcb = cb - 8; }
    else              { W = W3; bias = b3; out = o3; wstride = 64;  ostride = 64;  lcb = 0; }
    int colbase = lcb * 64;
    int rowbase = blockIdx.x * 64;
    int t = threadIdx.x;

    // stage W (scalar coalesced read, packed k-pair write)
    #pragma unroll
    for (int idx = t; idx < 4096; idx += 256) {
        int kk = idx >> 6, c = idx & 63;
        ((float*)&Bs2[c][kk >> 1])[kk & 1] = W[kk * wstride + colbase + c];
    }
    // stage X (float2 coalesced read)
    #pragma unroll
    for (int idx = t; idx < 2048; idx += 256) {
        int r = idx >> 5, kp = idx & 31;
        int gr = rowbase + r;
        F2U v; v.f = make_float2(0.0f, 0.0f);
        if (gr < N) v.f = *(const float2*)(X + (size_t)gr * HDIM + kp * 2);
        if (relu_in) { v.f.x = fmaxf(v.f.x, 0.0f); v.f.y = fmaxf(v.f.y, 0.0f); }
        As2[r][kp] = v.u;
    }
    __syncthreads();

    int tx = t & 15, ty = t >> 4;
    int r0 = ty * 4, c0 = tx * 4;
    ull acc[4][4];
    #pragma unroll
    for (int r = 0; r < 4; r++)
        #pragma unroll
        for (int c = 0; c < 4; c++) acc[r][c] = 0ull;

    #pragma unroll 8
    for (int kp = 0; kp < 32; kp++) {
        ull a0 = As2[r0 + 0][kp];
        ull a1 = As2[r0 + 1][kp];
        ull a2 = As2[r0 + 2][kp];
        ull a3 = As2[r0 + 3][kp];
        ull bb0 = Bs2[c0 + 0][kp];
        ull bb1 = Bs2[c0 + 1][kp];
        ull bb2 = Bs2[c0 + 2][kp];
        ull bb3 = Bs2[c0 + 3][kp];
        fma2(acc[0][0], a0, bb0); fma2(acc[0][1], a0, bb1); fma2(acc[0][2], a0, bb2); fma2(acc[0][3], a0, bb3);
        fma2(acc[1][0], a1, bb0); fma2(acc[1][1], a1, bb1); fma2(acc[1][2], a1, bb2); fma2(acc[1][3], a1, bb3);
        fma2(acc[2][0], a2, bb0); fma2(acc[2][1], a2, bb1); fma2(acc[2][2], a2, bb2); fma2(acc[2][3], a2, bb3);
        fma2(acc[3][0], a3, bb0); fma2(acc[3][1], a3, bb1); fma2(acc[3][2], a3, bb2); fma2(acc[3][3], a3, bb3);
    }

    float4 bb = *(const float4*)(bias + colbase + c0);
    #pragma unroll
    for (int r = 0; r < 4; r++) {
        int gr = rowbase + r0 + r;
        if (gr >= N) break;
        float4 res;
        res.x = hsum2(acc[r][0]) + bb.x;
        res.y = hsum2(acc[r][1]) + bb.y;
        res.z = hsum2(acc[r][2]) + bb.z;
        res.w = hsum2(acc[r][3]) + bb.w;
        *(float4*)(out + (size_t)gr * ostride + colbase + c0) = res;
    }
}

// Pass A: per-edge, per-head score = dot(q[dst,h], k[src,h]) / 8; atomicMax segment max.
__global__ void score_kernel(const int* __restrict__ esrc, const int* __restrict__ edst,
                             const float* __restrict__ q, const float* __restrict__ k,
                             float* __restrict__ score, unsigned* __restrict__ mmax,
                             int nedge) {
    int warp = (blockIdx.x * blockDim.x + threadIdx.x) >> 5;
    if (warp >= nedge) return;
    int lane = threadIdx.x & 31;
    int s = esrc[warp], d = edst[warp];
    int h = lane >> 3, sub = lane & 7;
    const float4* qp = (const float4*)(q + (size_t)d * QKDIM + h * HDIM + sub * 8);
    const float4* kp = (const float4*)(k + (size_t)s * QKDIM + h * HDIM + sub * 8);
    float4 q0 = qp[0], q1 = qp[1];
    float4 k0 = kp[0], k1 = kp[1];
    float dot = q0.x * k0.x + q0.y * k0.y + q0.z * k0.z + q0.w * k0.w
              + q1.x * k1.x + q1.y * k1.y + q1.z * k1.z + q1.w * k1.w;
    dot += __shfl_down_sync(0xffffffffu, dot, 4, 8);
    dot += __shfl_down_sync(0xffffffffu, dot, 2, 8);
    dot += __shfl_down_sync(0xffffffffu, dot, 1, 8);
    if (sub == 0) {
        float sc = dot * 0.125f;
        score[(size_t)warp * NHEADS + h] = sc;
        atomicMax(&mmax[(size_t)d * NHEADS + h], f2o(sc));
    }
}

// Pass B: e = exp(score - m[dst]); score <- e; denom[dst] += e.
__global__ void exp_kernel(const int* __restrict__ edst, const unsigned* __restrict__ mmax,
                           float* __restrict__ score, float* __restrict__ denom, int nedge) {
    int i = blockIdx.x * blockDim.x + threadIdx.x;
    if (i >= nedge * NHEADS) return;
    int e = i >> 2, h = i & 3;
    int d = edst[e];
    float m = o2f(mmax[(size_t)d * NHEADS + h]);
    float ex = __expf(score[i] - m);
    score[i] = ex;
    atomicAdd(&denom[(size_t)d * NHEADS + h], ex);
}

// Pass C: out[dst, 0:64] += (1/4) * sum_h alpha_h * v[src, h, 0:64]. Warp per edge.
__global__ void agg_kernel(const int* __restrict__ esrc, const int* __restrict__ edst,
                           const float* __restrict__ sc, const float* __restrict__ den,
                           const float* __restrict__ v, float* __restrict__ out, int nedge) {
    int warp = (blockIdx.x * blockDim.x + threadIdx.x) >> 5;
    if (warp >= nedge) return;
    int lane = threadIdx.x & 31;
    int s = esrc[warp], d = edst[warp];
    size_t eb = (size_t)warp * NHEADS, db = (size_t)d * NHEADS;
    float a0 = sc[eb + 0] / den[db + 0];
    float a1 = sc[eb + 1] / den[db + 1];
    float a2 = sc[eb + 2] / den[db + 2];
    float a3 = sc[eb + 3] / den[db + 3];
    const float2* vp = (const float2*)(v + (size_t)s * QKDIM);
    float2 v0 = vp[lane], v1 = vp[32 + lane], v2 = vp[64 + lane], v3 = vp[96 + lane];
    float ax = 0.25f * (a0 * v0.x + a1 * v1.x + a2 * v2.x + a3 * v3.x);
    float ay = 0.25f * (a0 * v0.y + a1 * v1.y + a2 * v2.y + a3 * v3.y);
    atomicAdd(&out[(size_t)d * HDIM + lane * 2 + 0], ax);
    atomicAdd(&out[(size_t)d * HDIM + lane * 2 + 1], ay);
}

// Classifier: pred[i] = dot(xs[l0[i]], xt[l1[i]]), 8 lanes per pair.
__global__ void pred_kernel(const int* __restrict__ l0, const int* __restrict__ l1,
                            const float* __restrict__ xs, const float* __restrict__ xt,
                            float* __restrict__ out, int n) {
    int gid = blockIdx.x * blockDim.x + threadIdx.x;
    int pair = gid >> 3, sub = gid & 7;
    if (pair >= n) return;
    int a = l0[pair], b = l1[pair];
    const float4* xa = (const float4*)(xs + (size_t)a * HDIM);
    const float4* xb = (const float4*)(xt + (size_t)b * HDIM);
    float4 p0 = xa[sub * 2], p1 = xa[sub * 2 + 1];
    float4 q0 = xb[sub * 2], q1 = xb[sub * 2 + 1];
    float dot = p0.x * q0.x + p0.y * q0.y + p0.z * q0.z + p0.w * q0.w
              + p1.x * q1.x + p1.y * q1.y + p1.z * q1.z + p1.w * q1.w;
    dot += __shfl_down_sync(0xffffffffu, dot, 4, 8);
    dot += __shfl_down_sync(0xffffffffu, dot, 2, 8);
    dot += __shfl_down_sync(0xffffffffu, dot, 1, 8);
    if (sub == 0) out[pair] = dot;
}

// ---------------- launch ----------------
extern "C" void kernel_launch(void* const* d_in, const int* in_sizes, int n_in,
                              void* d_out, int out_size) {
    const float* src_emb = (const float*)d_in[0];
    const float* tgt_emb = (const float*)d_in[1];
    const float* Wq = (const float*)d_in[2];
    const float* bq = (const float*)d_in[3];
    const float* Wk = (const float*)d_in[4];
    const float* bk = (const float*)d_in[5];
    const float* Wv = (const float*)d_in[6];
    const float* bv = (const float*)d_in[7];
    const float* Ws = (const float*)d_in[8];
    const float* bs = (const float*)d_in[9];
    const int* nid_s = (const int*)d_in[10];
    const int* nid_t = (const int*)d_in[11];
    const int* e_st  = (const int*)d_in[12];
    const int* e_ts  = (const int*)d_in[13];
    const int* lbl   = (const int*)d_in[14];
    float* out = (float*)d_out;

    float *xs_a, *xs_b, *xt_a, *xt_b;
    float *q_st, *k_ts, *v_ts, *q_ts, *k_st, *v_st;
    float *sc_st, *sc_ts, *d_st, *d_ts;
    unsigned *m_st, *m_ts;
    cudaGetSymbolAddress((void**)&xs_a, g_xs_a);
    cudaGetSymbolAddress((void**)&xs_b, g_xs_b);
    cudaGetSymbolAddress((void**)&xt_a, g_xt_a);
    cudaGetSymbolAddress((void**)&xt_b, g_xt_b);
    cudaGetSymbolAddress((void**)&q_st, g_q_st);
    cudaGetSymbolAddress((void**)&k_ts, g_k_ts);
    cudaGetSymbolAddress((void**)&v_ts, g_v_ts);
    cudaGetSymbolAddress((void**)&q_ts, g_q_ts);
    cudaGetSymbolAddress((void**)&k_st, g_k_st);
    cudaGetSymbolAddress((void**)&v_st, g_v_st);
    cudaGetSymbolAddress((void**)&sc_st, g_sc_st);
    cudaGetSymbolAddress((void**)&sc_ts, g_sc_ts);
    cudaGetSymbolAddress((void**)&m_st, g_m_st);
    cudaGetSymbolAddress((void**)&d_st, g_d_st);
    cudaGetSymbolAddress((void**)&m_ts, g_m_ts);
    cudaGetSymbolAddress((void**)&d_ts, g_d_ts);

    gather_rows<<<(N_SRC * HDIM + 255) / 256, 256>>>(src_emb, nid_s, xs_a, N_SRC);
    gather_rows<<<(N_TGT * HDIM + 255) / 256, 256>>>(tgt_emb, nid_t, xt_a, N_TGT);

    for (int l = 0; l < 2; l++) {
        float* in_s = l ? xs_b : xs_a;  float* out_s = l ? xs_a : xs_b;
        float* in_t = l ? xt_b : xt_a;  float* out_t = l ? xt_a : xt_b;

        int nz = (N_TGT + N_TGT + N_SRC + N_SRC) * NHEADS;
        zero4_kernel<<<(nz + 255) / 256, 256>>>((float*)m_st, N_TGT * NHEADS,
                                                d_st, N_TGT * NHEADS,
                                                (float*)m_ts, N_SRC * NHEADS,
                                                d_ts, N_SRC * NHEADS);

        dim3 gs((N_SRC + 63) / 64, 13), gt((N_TGT + 63) / 64, 13);
        // src-side projections: k_st (Wk[l,0]), v_st (Wv[l,0]), q_ts (Wq[l,1]), skip (Ws[l,1])
        proj_kernel<<<gs, 256>>>(in_s, N_SRC, l,
            Wk + (size_t)(l * 2 + 0) * 64 * 256, Wv + (size_t)(l * 2 + 0) * 64 * 256,
            Wq + (size_t)(l * 2 + 1) * 64 * 256, Ws + (size_t)(l * 2 + 1) * 64 * 64,
            bk + (l * 2 + 0) * 256, bv + (l * 2 + 0) * 256,
            bq + (l * 2 + 1) * 256, bs + (l * 2 + 1) * 64,
            k_st, v_st, q_ts, out_s);
        // tgt-side projections: q_st (Wq[l,0]), k_ts (Wk[l,1]), v_ts (Wv[l,1]), skip (Ws[l,0])
        proj_kernel<<<gt, 256>>>(in_t, N_TGT, l,
            Wq + (size_t)(l * 2 + 0) * 64 * 256, Wk + (size_t)(l * 2 + 1) * 64 * 256,
            Wv + (size_t)(l * 2 + 1) * 64 * 256, Ws + (size_t)(l * 2 + 0) * 64 * 64,
            bq + (l * 2 + 0) * 256, bk + (l * 2 + 1) * 256,
            bv + (l * 2 + 1) * 256, bs + (l * 2 + 0) * 64,
            q_st, k_ts, v_ts, out_t);

        int sb = (N_E * 32 + 255) / 256;  // one warp per edge
        score_kernel<<<sb, 256>>>(e_st, e_st + N_E, q_st, k_st, sc_st, m_st, N_E);
        score_kernel<<<sb, 256>>>(e_ts, e_ts + N_E, q_ts, k_ts, sc_ts, m_ts, N_E);

        int eb = (N_E * NHEADS + 255) / 256;
        exp_kernel<<<eb, 256>>>(e_st + N_E, m_st, sc_st, d_st, N_E);
        exp_kernel<<<eb, 256>>>(e_ts + N_E, m_ts, sc_ts, d_ts, N_E);

        agg_kernel<<<sb, 256>>>(e_st, e_st + N_E, sc_st, d_st, v_st, out_t, N_E);
        agg_kernel<<<sb, 256>>>(e_ts, e_ts + N_E, sc_ts, d_ts, v_ts, out_s, N_E);
        // note: layer-0 ReLU is fused into the layer-1 proj input load (relu_in=l)
    }

    // after layer 1, final embeddings live in the *_a buffers
    pred_kernel<<<(N_LBL * 8 + 255) / 256, 256>>>(lbl, lbl + N_LBL, xs_a, xt_a, out, N_LBL);
}

// round 3
// speedup vs baseline: 1.6917x; 1.6917x over previous
#include <cuda_runtime.h>
#include <cuda_bf16.h>

#define HDIM   64
#define NHEADS 4
#define QKDIM  256           // NHEADS * HDIM
#define N_SRC  50000
#define N_TGT  10000
#define N_E    250000
#define N_LBL  200000

#define PADK   72            // smem row stride in bf16 (144B): ldmatrix conflict-free
#define WSECT  (832 * 64)    // per (layer,edge_type) transposed weight block (elements)

// ---------------- scratch (static device memory; no allocations) ----------------
__device__ float g_xs_a[N_SRC * HDIM];
__device__ float g_xs_b[N_SRC * HDIM];
__device__ float g_xt_a[N_TGT * HDIM];
__device__ float g_xt_b[N_TGT * HDIM];

__device__ float g_q_st[N_TGT * QKDIM];
__device__ float g_k_ts[N_TGT * QKDIM];
__device__ float g_v_ts[N_TGT * QKDIM];
__device__ float g_q_ts[N_SRC * QKDIM];
__device__ float g_k_st[N_SRC * QKDIM];
__device__ float g_v_st[N_SRC * QKDIM];

__device__ float    g_sc_st[N_E * NHEADS];
__device__ float    g_sc_ts[N_E * NHEADS];
__device__ unsigned g_m_st[N_TGT * NHEADS];
__device__ float    g_d_st[N_TGT * NHEADS];
__device__ unsigned g_m_ts[N_SRC * NHEADS];
__device__ float    g_d_ts[N_SRC * NHEADS];

// split-bf16 operands
__device__ __nv_bfloat16 g_xsh[N_SRC * HDIM];
__device__ __nv_bfloat16 g_xsl[N_SRC * HDIM];
__device__ __nv_bfloat16 g_xth[N_TGT * HDIM];
__device__ __nv_bfloat16 g_xtl[N_TGT * HDIM];
__device__ __nv_bfloat16 g_wth[4 * WSECT];   // transposed [n832][64] hi, per (l,et)
__device__ __nv_bfloat16 g_wtl[4 * WSECT];   // lo

// ---------------- helpers ----------------
__device__ __forceinline__ unsigned f2o(float f) {
    unsigned u = __float_as_uint(f);
    return (u & 0x80000000u) ? ~u : (u | 0x80000000u);
}
__device__ __forceinline__ float o2f(unsigned u) {
    u = (u & 0x80000000u) ? (u & 0x7fffffffu) : ~u;
    return __uint_as_float(u);
}
__device__ __forceinline__ void split2(float v, __nv_bfloat16& h, __nv_bfloat16& l) {
    h = __float2bfloat16(v);
    l = __float2bfloat16(v - __bfloat162float(h));
}
__device__ __forceinline__ unsigned su32(const void* p) {
    unsigned a;
    asm("{ .reg .u64 t; cvta.to.shared.u64 t, %1; cvt.u32.u64 %0, t; }" : "=r"(a) : "l"(p));
    return a;
}
__device__ __forceinline__ void ldsm4(unsigned& r0, unsigned& r1, unsigned& r2, unsigned& r3,
                                      unsigned addr) {
    asm volatile("ldmatrix.sync.aligned.m8n8.x4.shared.b16 {%0,%1,%2,%3}, [%4];"
                 : "=r"(r0), "=r"(r1), "=r"(r2), "=r"(r3) : "r"(addr));
}
__device__ __forceinline__ void mma16816(float* d, const unsigned* a, unsigned b0, unsigned b1) {
    asm volatile("mma.sync.aligned.m16n8k16.row.col.f32.bf16.bf16.f32 "
                 "{%0,%1,%2,%3}, {%4,%5,%6,%7}, {%8,%9}, {%0,%1,%2,%3};"
                 : "+f"(d[0]), "+f"(d[1]), "+f"(d[2]), "+f"(d[3])
                 : "r"(a[0]), "r"(a[1]), "r"(a[2]), "r"(a[3]), "r"(b0), "r"(b1));
}

// ---------------- small kernels ----------------
__global__ void zero4_kernel(float* __restrict__ a, int na, float* __restrict__ b, int nb,
                             float* __restrict__ c, int nc, float* __restrict__ d, int nd) {
    int i = blockIdx.x * blockDim.x + threadIdx.x;
    if (i < na) { a[i] = 0.0f; return; }
    i -= na;
    if (i < nb) { b[i] = 0.0f; return; }
    i -= nb;
    if (i < nc) { c[i] = 0.0f; return; }
    i -= nc;
    if (i < nd) d[i] = 0.0f;
}

__global__ void gather_split(const float* __restrict__ emb, const int* __restrict__ ids,
                             __nv_bfloat16* __restrict__ xh, __nv_bfloat16* __restrict__ xl,
                             int nrows) {
    int i = blockIdx.x * blockDim.x + threadIdx.x;
    if (i >= nrows * HDIM) return;
    int row = i >> 6, d = i & 63;
    float v = emb[(size_t)ids[row] * HDIM + d];
    split2(v, xh[i], xl[i]);
}

__global__ void relu_split(const float* __restrict__ x,
                           __nv_bfloat16* __restrict__ xh, __nv_bfloat16* __restrict__ xl, int n) {
    int i = blockIdx.x * blockDim.x + threadIdx.x;
    if (i >= n) return;
    float v = fmaxf(x[i], 0.0f);
    split2(v, xh[i], xl[i]);
}

// Transpose + split all weights once: wt[(le)*WSECT + n832*64 + k], n832: [Wq|Wk|Wv|Ws]
__global__ void split_w(const float* __restrict__ Wq, const float* __restrict__ Wk,
                        const float* __restrict__ Wv, const float* __restrict__ Ws,
                        __nv_bfloat16* __restrict__ wth, __nv_bfloat16* __restrict__ wtl) {
    int i = blockIdx.x * blockDim.x + threadIdx.x;
    if (i >= 4 * WSECT) return;
    int le = i / WSECT, rem = i % WSECT;
    int n = rem >> 6, k = rem & 63;
    float v;
    if (n < 256)      v = Wq[(size_t)le * 64 * 256 + k * 256 + n];
    else if (n < 512) v = Wk[(size_t)le * 64 * 256 + k * 256 + (n - 256)];
    else if (n < 768) v = Wv[(size_t)le * 64 * 256 + k * 256 + (n - 512)];
    else              v = Ws[(size_t)le * 64 * 64 + k * 64 + (n - 768)];
    split2(v, wth[i], wtl[i]);
}

// ---------------- tensor-core projection GEMM ----------------
// X[N,64] (split bf16) x W^T sections -> q/k/v [N,256] + skip [N,64], fp32 out.
// 128x64 tile, 8 warps (32x32 each), K=64, split-bf16: Ah*Bh + Ah*Bl + Al*Bh.
__global__ void __launch_bounds__(256) proj_mma(
    const __nv_bfloat16* __restrict__ Xh, const __nv_bfloat16* __restrict__ Xl, int N,
    const __nv_bfloat16* __restrict__ Wth, const __nv_bfloat16* __restrict__ Wtl,
    int off0, int off1, int off2, int off3,
    const float* __restrict__ b0, const float* __restrict__ b1,
    const float* __restrict__ b2, const float* __restrict__ b3,
    float* __restrict__ o0, float* __restrict__ o1,
    float* __restrict__ o2, float* __restrict__ o3) {
    extern __shared__ __nv_bfloat16 sm[];
    __nv_bfloat16* Ah = sm;                    // [128][PADK]
    __nv_bfloat16* Al = Ah + 128 * PADK;
    __nv_bfloat16* Bh = Al + 128 * PADK;       // [64][PADK]
    __nv_bfloat16* Bl = Bh + 64 * PADK;

    int cb = blockIdx.y;                       // 0..12
    int sec = cb >> 2;                         // 0..3 (cb=12 -> 3)
    int lcb = cb & 3;                          // 0..3 (cb=12 -> 0)
    int woff, ostride; const float* bias; float* out;
    if (sec == 0)      { woff = off0; bias = b0; out = o0; ostride = 256; }
    else if (sec == 1) { woff = off1; bias = b1; out = o1; ostride = 256; }
    else if (sec == 2) { woff = off2; bias = b2; out = o2; ostride = 256; }
    else               { woff = off3; bias = b3; out = o3; ostride = 64;  }
    woff += lcb * 64 * 64;                     // 64 output rows (n) of 64 k each

    int t = threadIdx.x;
    int rowbase = blockIdx.x * 128;

    // stage A (hi/lo): 128 rows x 128B each, uint4 chunks
    const uint4* xh4 = (const uint4*)Xh;
    const uint4* xl4 = (const uint4*)Xl;
    uint4 z4 = make_uint4(0u, 0u, 0u, 0u);
    #pragma unroll
    for (int i = 0; i < 4; i++) {
        int idx = t + i * 256;                 // 0..1023
        int r = idx >> 3, c = idx & 7;
        int gr = rowbase + r;
        uint4 vh = z4, vl = z4;
        if (gr < N) { vh = xh4[(size_t)gr * 8 + c]; vl = xl4[(size_t)gr * 8 + c]; }
        *(uint4*)(Ah + r * PADK + c * 8) = vh;
        *(uint4*)(Al + r * PADK + c * 8) = vl;
    }
    // stage B (hi/lo): 64 rows (n) x 128B
    const uint4* wh4 = (const uint4*)(Wth + woff);
    const uint4* wl4 = (const uint4*)(Wtl + woff);
    #pragma unroll
    for (int i = 0; i < 2; i++) {
        int idx = t + i * 256;                 // 0..511
        int n = idx >> 3, c = idx & 7;
        *(uint4*)(Bh + n * PADK + c * 8) = wh4[n * 8 + c];
        *(uint4*)(Bl + n * PADK + c * 8) = wl4[n * 8 + c];
    }
    __syncthreads();

    int lane = t & 31, warp = t >> 5;
    int wr = warp >> 1, wc = warp & 1;         // 4 row-warps x 2 col-warps
    int lrow = lane & 7, lsel = lane >> 3;     // ldmatrix lane decomposition

    float acc[2][4][4];
    #pragma unroll
    for (int mt = 0; mt < 2; mt++)
        #pragma unroll
        for (int nt = 0; nt < 4; nt++)
            #pragma unroll
            for (int r = 0; r < 4; r++) acc[mt][nt][r] = 0.0f;

    unsigned ah_u = su32(Ah), al_u = su32(Al), bh_u = su32(Bh), bl_u = su32(Bl);

    #pragma unroll
    for (int kc = 0; kc < 4; kc++) {
        int k0 = kc * 16;
        unsigned ah[2][4], al[2][4], bh[2][4], bl[2][4];
        #pragma unroll
        for (int mt = 0; mt < 2; mt++) {
            int row = wr * 32 + mt * 16 + (lsel & 1) * 8 + lrow;
            int koff = k0 + (lsel >> 1) * 8;
            unsigned boff = (unsigned)(row * PADK + koff) * 2u;
            ldsm4(ah[mt][0], ah[mt][1], ah[mt][2], ah[mt][3], ah_u + boff);
            ldsm4(al[mt][0], al[mt][1], al[mt][2], al[mt][3], al_u + boff);
        }
        #pragma unroll
        for (int nt2 = 0; nt2 < 2; nt2++) {
            int n = wc * 32 + nt2 * 16 + (lsel >> 1) * 8 + lrow;
            int koff = k0 + (lsel & 1) * 8;
            unsigned boff = (unsigned)(n * PADK + koff) * 2u;
            ldsm4(bh[nt2][0], bh[nt2][1], bh[nt2][2], bh[nt2][3], bh_u + boff);
            ldsm4(bl[nt2][0], bl[nt2][1], bl[nt2][2], bl[nt2][3], bl_u + boff);
        }
        #pragma unroll
        for (int mt = 0; mt < 2; mt++)
            #pragma unroll
            for (int nt = 0; nt < 4; nt++) {
                int g = nt >> 1, hf = (nt & 1) * 2;
                mma16816(acc[mt][nt], ah[mt], bh[g][hf], bh[g][hf + 1]);   // Ah*Bh
                mma16816(acc[mt][nt], ah[mt], bl[g][hf], bl[g][hf + 1]);   // Ah*Bl
                mma16816(acc[mt][nt], al[mt], bh[g][hf], bh[g][hf + 1]);   // Al*Bh
            }
    }

    // epilogue: bias + fp32 store
    #pragma unroll
    for (int mt = 0; mt < 2; mt++) {
        int ra = rowbase + wr * 32 + mt * 16 + (lane >> 2);
        int rb = ra + 8;
        #pragma unroll
        for (int nt = 0; nt < 4; nt++) {
            int col = lcb * 64 + wc * 32 + nt * 8 + (lane & 3) * 2;
            float2 bv = *(const float2*)(bias + col);
            if (ra < N)
                *(float2*)(out + (size_t)ra * ostride + col) =
                    make_float2(acc[mt][nt][0] + bv.x, acc[mt][nt][1] + bv.y);
            if (rb < N)
                *(float2*)(out + (size_t)rb * ostride + col) =
                    make_float2(acc[mt][nt][2] + bv.x, acc[mt][nt][3] + bv.y);
        }
    }
}

// ---------------- edge kernels (known-good) ----------------
__global__ void score_kernel(const int* __restrict__ esrc, const int* __restrict__ edst,
                             const float* __restrict__ q, const float* __restrict__ k,
                             float* __restrict__ score, unsigned* __restrict__ mmax,
                             int nedge) {
    int warp = (blockIdx.x * blockDim.x + threadIdx.x) >> 5;
    if (warp >= nedge) return;
    int lane = threadIdx.x & 31;
    int s = esrc[warp], d = edst[warp];
    int h = lane >> 3, sub = lane & 7;
    const float4* qp = (const float4*)(q + (size_t)d * QKDIM + h * HDIM + sub * 8);
    const float4* kp = (const float4*)(k + (size_t)s * QKDIM + h * HDIM + sub * 8);
    float4 q0 = qp[0], q1 = qp[1];
    float4 k0 = kp[0], k1 = kp[1];
    float dot = q0.x * k0.x + q0.y * k0.y + q0.z * k0.z + q0.w * k0.w
              + q1.x * k1.x + q1.y * k1.y + q1.z * k1.z + q1.w * k1.w;
    dot += __shfl_down_sync(0xffffffffu, dot, 4, 8);
    dot += __shfl_down_sync(0xffffffffu, dot, 2, 8);
    dot += __shfl_down_sync(0xffffffffu, dot, 1, 8);
    if (sub == 0) {
        float sc = dot * 0.125f;
        score[(size_t)warp * NHEADS + h] = sc;
        atomicMax(&mmax[(size_t)d * NHEADS + h], f2o(sc));
    }
}

__global__ void exp_kernel(const int* __restrict__ edst, const unsigned* __restrict__ mmax,
                           float* __restrict__ score, float* __restrict__ denom, int nedge) {
    int i = blockIdx.x * blockDim.x + threadIdx.x;
    if (i >= nedge * NHEADS) return;
    int e = i >> 2, h = i & 3;
    int d = edst[e];
    float m = o2f(mmax[(size_t)d * NHEADS + h]);
    float ex = __expf(score[i] - m);
    score[i] = ex;
    atomicAdd(&denom[(size_t)d * NHEADS + h], ex);
}

__global__ void agg_kernel(const int* __restrict__ esrc, const int* __restrict__ edst,
                           const float* __restrict__ sc, const float* __restrict__ den,
                           const float* __restrict__ v, float* __restrict__ out, int nedge) {
    int warp = (blockIdx.x * blockDim.x + threadIdx.x) >> 5;
    if (warp >= nedge) return;
    int lane = threadIdx.x & 31;
    int s = esrc[warp], d = edst[warp];
    size_t eb = (size_t)warp * NHEADS, db = (size_t)d * NHEADS;
    float a0 = sc[eb + 0] / den[db + 0];
    float a1 = sc[eb + 1] / den[db + 1];
    float a2 = sc[eb + 2] / den[db + 2];
    float a3 = sc[eb + 3] / den[db + 3];
    const float2* vp = (const float2*)(v + (size_t)s * QKDIM);
    float2 v0 = vp[lane], v1 = vp[32 + lane], v2 = vp[64 + lane], v3 = vp[96 + lane];
    float ax = 0.25f * (a0 * v0.x + a1 * v1.x + a2 * v2.x + a3 * v3.x);
    float ay = 0.25f * (a0 * v0.y + a1 * v1.y + a2 * v2.y + a3 * v3.y);
    atomicAdd(&out[(size_t)d * HDIM + lane * 2 + 0], ax);
    atomicAdd(&out[(size_t)d * HDIM + lane * 2 + 1], ay);
}

__global__ void pred_kernel(const int* __restrict__ l0, const int* __restrict__ l1,
                            const float* __restrict__ xs, const float* __restrict__ xt,
                            float* __restrict__ out, int n) {
    int gid = blockIdx.x * blockDim.x + threadIdx.x;
    int pair = gid >> 3, sub = gid & 7;
    if (pair >= n) return;
    int a = l0[pair], b = l1[pair];
    const float4* xa = (const float4*)(xs + (size_t)a * HDIM);
    const float4* xb = (const float4*)(xt + (size_t)b * HDIM);
    float4 p0 = xa[sub * 2], p1 = xa[sub * 2 + 1];
    float4 q0 = xb[sub * 2], q1 = xb[sub * 2 + 1];
    float dot = p0.x * q0.x + p0.y * q0.y + p0.z * q0.z + p0.w * q0.w
              + p1.x * q1.x + p1.y * q1.y + p1.z * q1.z + p1.w * q1.w;
    dot += __shfl_down_sync(0xffffffffu, dot, 4, 8);
    dot += __shfl_down_sync(0xffffffffu, dot, 2, 8);
    dot += __shfl_down_sync(0xffffffffu, dot, 1, 8);
    if (sub == 0) out[pair] = dot;
}

// ---------------- launch ----------------
extern "C" void kernel_launch(void* const* d_in, const int* in_sizes, int n_in,
                              void* d_out, int out_size) {
    const float* src_emb = (const float*)d_in[0];
    const float* tgt_emb = (const float*)d_in[1];
    const float* Wq = (const float*)d_in[2];
    const float* bq = (const float*)d_in[3];
    const float* Wk = (const float*)d_in[4];
    const float* bk = (const float*)d_in[5];
    const float* Wv = (const float*)d_in[6];
    const float* bv = (const float*)d_in[7];
    const float* Ws = (const float*)d_in[8];
    const float* bs = (const float*)d_in[9];
    const int* nid_s = (const int*)d_in[10];
    const int* nid_t = (const int*)d_in[11];
    const int* e_st  = (const int*)d_in[12];
    const int* e_ts  = (const int*)d_in[13];
    const int* lbl   = (const int*)d_in[14];
    float* out = (float*)d_out;

    float *xs_a, *xs_b, *xt_a, *xt_b;
    float *q_st, *k_ts, *v_ts, *q_ts, *k_st, *v_st;
    float *sc_st, *sc_ts, *d_st, *d_ts;
    unsigned *m_st, *m_ts;
    __nv_bfloat16 *xsh, *xsl, *xth, *xtl, *wth, *wtl;
    cudaGetSymbolAddress((void**)&xs_a, g_xs_a);
    cudaGetSymbolAddress((void**)&xs_b, g_xs_b);
    cudaGetSymbolAddress((void**)&xt_a, g_xt_a);
    cudaGetSymbolAddress((void**)&xt_b, g_xt_b);
    cudaGetSymbolAddress((void**)&q_st, g_q_st);
    cudaGetSymbolAddress((void**)&k_ts, g_k_ts);
    cudaGetSymbolAddress((void**)&v_ts, g_v_ts);
    cudaGetSymbolAddress((void**)&q_ts, g_q_ts);
    cudaGetSymbolAddress((void**)&k_st, g_k_st);
    cudaGetSymbolAddress((void**)&v_st, g_v_st);
    cudaGetSymbolAddress((void**)&sc_st, g_sc_st);
    cudaGetSymbolAddress((void**)&sc_ts, g_sc_ts);
    cudaGetSymbolAddress((void**)&m_st, g_m_st);
    cudaGetSymbolAddress((void**)&d_st, g_d_st);
    cudaGetSymbolAddress((void**)&m_ts, g_m_ts);
    cudaGetSymbolAddress((void**)&d_ts, g_d_ts);
    cudaGetSymbolAddress((void**)&xsh, g_xsh);
    cudaGetSymbolAddress((void**)&xsl, g_xsl);
    cudaGetSymbolAddress((void**)&xth, g_xth);
    cudaGetSymbolAddress((void**)&xtl, g_xtl);
    cudaGetSymbolAddress((void**)&wth, g_wth);
    cudaGetSymbolAddress((void**)&wtl, g_wtl);

    const int SMEM = (128 * PADK * 2 + 64 * PADK * 2) * 2;  // 55296 B
    cudaFuncSetAttribute(proj_mma, cudaFuncAttributeMaxDynamicSharedMemorySize, SMEM);

    gather_split<<<(N_SRC * HDIM + 255) / 256, 256>>>(src_emb, nid_s, xsh, xsl, N_SRC);
    gather_split<<<(N_TGT * HDIM + 255) / 256, 256>>>(tgt_emb, nid_t, xth, xtl, N_TGT);
    split_w<<<(4 * WSECT + 255) / 256, 256>>>(Wq, Wk, Wv, Ws, wth, wtl);

    for (int l = 0; l < 2; l++) {
        float* out_s = l ? xs_a : xs_b;
        float* out_t = l ? xt_a : xt_b;
        if (l) {
            relu_split<<<(N_SRC * HDIM + 255) / 256, 256>>>(xs_b, xsh, xsl, N_SRC * HDIM);
            relu_split<<<(N_TGT * HDIM + 255) / 256, 256>>>(xt_b, xth, xtl, N_TGT * HDIM);
        }

        int nz = (N_TGT + N_TGT + N_SRC + N_SRC) * NHEADS;
        zero4_kernel<<<(nz + 255) / 256, 256>>>((float*)m_st, N_TGT * NHEADS,
                                                d_st, N_TGT * NHEADS,
                                                (float*)m_ts, N_SRC * NHEADS,
                                                d_ts, N_SRC * NHEADS);

        int le0 = l * 2 + 0, le1 = l * 2 + 1;
        dim3 gs((N_SRC + 127) / 128, 13), gt((N_TGT + 127) / 128, 13);
        // src-side: k_st(Wk l,0), v_st(Wv l,0), q_ts(Wq l,1), skip(Ws l,1)
        proj_mma<<<gs, 256, SMEM>>>(xsh, xsl, N_SRC, wth, wtl,
            le0 * WSECT + 256 * 64, le0 * WSECT + 512 * 64,
            le1 * WSECT + 0,        le1 * WSECT + 768 * 64,
            bk + le0 * 256, bv + le0 * 256, bq + le1 * 256, bs + le1 * 64,
            k_st, v_st, q_ts, out_s);
        // tgt-side: q_st(Wq l,0), k_ts(Wk l,1), v_ts(Wv l,1), skip(Ws l,0)
        proj_mma<<<gt, 256, SMEM>>>(xth, xtl, N_TGT, wth, wtl,
            le0 * WSECT + 0,        le1 * WSECT + 256 * 64,
            le1 * WSECT + 512 * 64, le0 * WSECT + 768 * 64,
            bq + le0 * 256, bk + le1 * 256, bv + le1 * 256, bs + le0 * 64,
            q_st, k_ts, v_ts, out_t);

        int sb = (N_E * 32 + 255) / 256;  // one warp per edge
        score_kernel<<<sb, 256>>>(e_st, e_st + N_E, q_st, k_st, sc_st, m_st, N_E);
        score_kernel<<<sb, 256>>>(e_ts, e_ts + N_E, q_ts, k_ts, sc_ts, m_ts, N_E);

        int eb = (N_E * NHEADS + 255) / 256;
        exp_kernel<<<eb, 256>>>(e_st + N_E, m_st, sc_st, d_st, N_E);
        exp_kernel<<<eb, 256>>>(e_ts + N_E, m_ts, sc_ts, d_ts, N_E);

        agg_kernel<<<sb, 256>>>(e_st, e_st + N_E, sc_st, d_st, v_st, out_t, N_E);
        agg_kernel<<<sb, 256>>>(e_ts, e_ts + N_E, sc_ts, d_ts, v_ts, out_s, N_E);
    }

    pred_kernel<<<(N_LBL * 8 + 255) / 256, 256>>>(lbl, lbl + N_LBL, xs_a, xt_a, out, N_LBL);
}